// round 1
// baseline (speedup 1.0000x reference)
#include <cuda_runtime.h>
#include <math.h>
#include <float.h>

#define B 8
#define SEQ 12
#define NN 1000
#define E 16000
#define HID 128
#define HEADS 8
#define DH 16
#define M_ROWS (B*NN)          /* 8000 */
#define CAP 64

// ---------------- static device scratch (no allocations allowed) ----------------
__device__ float g_hin[(size_t)SEQ*B*NN*HID];   // layout [SEQ][B][N][HID]
__device__ float g_y  [(size_t)M_ROWS*HID];
__device__ float g_hp [(size_t)M_ROWS*HID];
__device__ float g_k1 [(size_t)M_ROWS*HID];
__device__ float g_k2 [(size_t)M_ROWS*HID];
__device__ float g_k3 [(size_t)M_ROWS*HID];
__device__ float g_k4 [(size_t)M_ROWS*HID];
__device__ float g_tmp[(size_t)M_ROWS*HID];
__device__ int   g_cnt[NN];
__device__ int   g_cur[NN];
__device__ int   g_off[NN+1];
__device__ int   g_eidx[E];

// ---------------- CSR construction (deterministic: sorted edge ids) ----------------
__global__ void k_csr_zero(int* cnt, int* cur){
    int i = blockIdx.x*blockDim.x + threadIdx.x;
    if (i < NN){ cnt[i]=0; cur[i]=0; }
}
__global__ void k_csr_count(const int* __restrict__ dst, int* cnt){
    int e = blockIdx.x*blockDim.x + threadIdx.x;
    if (e < E) atomicAdd(&cnt[dst[e]], 1);
}
__global__ void k_csr_scan(const int* __restrict__ cnt, int* off){
    __shared__ int s[1024];
    int t = threadIdx.x;
    s[t] = (t < NN) ? cnt[t] : 0;
    __syncthreads();
    #pragma unroll
    for (int o = 1; o < 1024; o <<= 1){
        int v = (t >= o) ? s[t-o] : 0;
        __syncthreads();
        s[t] += v;
        __syncthreads();
    }
    if (t == 0) off[0] = 0;
    if (t < NN) off[t+1] = s[t];
}
__global__ void k_csr_fill(const int* __restrict__ dst, const int* __restrict__ off,
                           int* cur, int* eidx){
    int e = blockIdx.x*blockDim.x + threadIdx.x;
    if (e < E){
        int d = dst[e];
        int p = atomicAdd(&cur[d], 1);
        eidx[off[d] + p] = e;
    }
}
__global__ void k_csr_sort(const int* __restrict__ off, int* eidx){
    if (threadIdx.x != 0) return;
    int n = blockIdx.x;
    int a = off[n], b = off[n+1];
    for (int i = a+1; i < b; i++){
        int v = eidx[i]; int j = i-1;
        while (j >= a && eidx[j] > v){ eidx[j+1] = eidx[j]; j--; }
        eidx[j+1] = v;
    }
}

// ---------------- input projection: h = inputs @ w_in + b_in ----------------
// inputs [B][SEQ][N][2]  ->  g_hin [SEQ][B][N][HID]
__global__ void k_inproj(const float* __restrict__ inp, const float* __restrict__ w_in,
                         const float* __restrict__ b_in, float* __restrict__ hin){
    int row = blockIdx.x;                 // over B*SEQ*NN in input order
    int t = threadIdx.x;
    int b = row / (SEQ*NN);
    int s = (row / NN) % SEQ;
    int n = row % NN;
    float x0 = inp[(size_t)row*2 + 0];
    float x1 = inp[(size_t)row*2 + 1];
    size_t o = (((size_t)s*B + b)*NN + n)*HID + t;
    hin[o] = fmaf(x0, w_in[t], fmaf(x1, w_in[HID+t], b_in[t]));
}

__global__ void k_copy(const float* __restrict__ a, float* __restrict__ b, int n){
    int i = blockIdx.x*blockDim.x + threadIdx.x;
    if (i < n) b[i] = a[i];
}

// ---------------- generic GEMM: C = act( (A0 + c1*A1)@W0 [+ A2@W1] + b0 + b1 ) ----------------
// M = 8000, K = N = 128.  grid (125, 2), 128 threads. Per-thread 8x4 micro-tile.
__global__ void __launch_bounds__(128) k_gemm(
    const float* __restrict__ A0, const float* __restrict__ A1, float c1,
    const float* __restrict__ W0,
    const float* __restrict__ A2, const float* __restrict__ W1,
    const float* __restrict__ b0, const float* __restrict__ b1,
    float* __restrict__ C, int act)
{
    __shared__ float sA[64][HID];
    int row0    = blockIdx.x * 64;
    int colBase = blockIdx.y * 64;
    int tid = threadIdx.x;
    int tx = tid & 15, ty = tid >> 4;
    int col0 = colBase + tx*4;

    float acc[8][4];
    #pragma unroll
    for (int i=0;i<8;i++)
        #pragma unroll
        for (int j=0;j<4;j++) acc[i][j] = 0.f;

    // ---- product 0 ----
    for (int i = tid; i < 64*HID; i += 128){
        int r = i >> 7, c = i & 127;
        size_t gi = (size_t)(row0 + r)*HID + c;
        float v = A0[gi];
        if (A1) v = fmaf(c1, A1[gi], v);
        sA[r][c] = v;
    }
    __syncthreads();
    {
        const float* Wp = W0 + col0;
        #pragma unroll 4
        for (int k = 0; k < HID; k++){
            float4 w = *reinterpret_cast<const float4*>(Wp + (size_t)k*HID);
            #pragma unroll
            for (int i = 0; i < 8; i++){
                float a = sA[ty*8+i][k];
                acc[i][0] = fmaf(a, w.x, acc[i][0]);
                acc[i][1] = fmaf(a, w.y, acc[i][1]);
                acc[i][2] = fmaf(a, w.z, acc[i][2]);
                acc[i][3] = fmaf(a, w.w, acc[i][3]);
            }
        }
    }
    // ---- optional product 1 ----
    if (A2){
        __syncthreads();
        for (int i = tid; i < 64*HID; i += 128){
            int r = i >> 7, c = i & 127;
            sA[r][c] = A2[(size_t)(row0 + r)*HID + c];
        }
        __syncthreads();
        const float* Wp = W1 + col0;
        #pragma unroll 4
        for (int k = 0; k < HID; k++){
            float4 w = *reinterpret_cast<const float4*>(Wp + (size_t)k*HID);
            #pragma unroll
            for (int i = 0; i < 8; i++){
                float a = sA[ty*8+i][k];
                acc[i][0] = fmaf(a, w.x, acc[i][0]);
                acc[i][1] = fmaf(a, w.y, acc[i][1]);
                acc[i][2] = fmaf(a, w.z, acc[i][2]);
                acc[i][3] = fmaf(a, w.w, acc[i][3]);
            }
        }
    }
    // ---- epilogue ----
    float bias[4] = {0.f,0.f,0.f,0.f};
    if (b0){
        #pragma unroll
        for (int j=0;j<4;j++) bias[j] += b0[col0+j];
    }
    if (b1){
        #pragma unroll
        for (int j=0;j<4;j++) bias[j] += b1[col0+j];
    }
    #pragma unroll
    for (int i = 0; i < 8; i++){
        int r = row0 + ty*8 + i;
        float4 o;
        o.x = acc[i][0] + bias[0];
        o.y = acc[i][1] + bias[1];
        o.z = acc[i][2] + bias[2];
        o.w = acc[i][3] + bias[3];
        if (act){
            o.x = tanhf(o.x); o.y = tanhf(o.y); o.z = tanhf(o.z); o.w = tanhf(o.w);
        }
        *reinterpret_cast<float4*>(C + (size_t)r*HID + col0) = o;
    }
}

// ---------------- GAT node kernel: edge softmax + aggregation, atomic-free ----------------
// block = (b,n) destination node, 128 threads (head = tid>>4, lane = tid&15)
__global__ void __launch_bounds__(128) k_gat(
    const float* __restrict__ hp,
    const float* __restrict__ a_l, const float* __restrict__ a_r,
    const int* __restrict__ off, const int* __restrict__ eidx,
    const int* __restrict__ src,
    float* __restrict__ kout)
{
    int bn = blockIdx.x;
    int b = bn / NN, n = bn - b*NN;
    int tid = threadIdx.x;
    int head = tid >> 4, lane = tid & 15;

    __shared__ float s_hs[CAP][HID];
    __shared__ float s_e [CAP][HEADS];
    __shared__ float s_max[HEADS];
    __shared__ int   s_src[CAP];

    const float al = a_l[tid];   // a_l[head][lane] row-major == a_l[tid]
    const float ar = a_r[tid];
    const float* hb = hp + (size_t)b*NN*HID;

    // er for this destination node (all 16 lanes of the head group end with the sum)
    float er = hb[(size_t)n*HID + tid] * ar;
    #pragma unroll
    for (int o = 8; o > 0; o >>= 1) er += __shfl_xor_sync(0xffffffffu, er, o);

    int e0 = off[n], e1 = off[n+1];
    int deg = e1 - e0;

    float acc    = 0.f;
    float runmax = -FLT_MAX;
    float runsum = 0.f;

    for (int base = 0; base < deg; base += CAP){
        int cnt = min(CAP, deg - base);
        if (tid < cnt) s_src[tid] = src[eidx[e0 + base + tid]];
        __syncthreads();

        for (int j = 0; j < cnt; j++){
            float h = hb[(size_t)s_src[j]*HID + tid];
            s_hs[j][tid] = h;
            float u = h * al;
            #pragma unroll
            for (int o = 8; o > 0; o >>= 1) u += __shfl_xor_sync(0xffffffffu, u, o);
            if (lane == 0){
                float e = u + er;
                s_e[j][head] = (e >= 0.f) ? e : 0.2f*e;   // leaky_relu
            }
        }
        __syncthreads();

        if (tid < HEADS){
            float m = -FLT_MAX;
            for (int j = 0; j < cnt; j++) m = fmaxf(m, s_e[j][tid]);
            s_max[tid] = m;
        }
        __syncthreads();

        float newmax = fmaxf(runmax, s_max[head]);
        float scale  = (runmax == -FLT_MAX) ? 0.f : expf(runmax - newmax);
        acc    *= scale;
        runsum *= scale;
        for (int j = 0; j < cnt; j++){
            float w = expf(s_e[j][head] - newmax);
            runsum += w;
            acc = fmaf(w, s_hs[j][tid], acc);
        }
        runmax = newmax;
        __syncthreads();
    }
    // alpha = w/(sum+1e-16); sum_j alpha_j*h_j == acc/(sum+1e-16)
    kout[(size_t)bn*HID + tid] = acc / (runsum + 1e-16f);
}

// ---------------- RK4 combine: y += dt/6 * (k1 + 2k2 + 2k3 + k4) ----------------
__global__ void k_combine(float* __restrict__ y,
                          const float* __restrict__ k1, const float* __restrict__ k2,
                          const float* __restrict__ k3, const float* __restrict__ k4){
    int i = blockIdx.x*blockDim.x + threadIdx.x;
    if (i < M_ROWS*HID){
        const float c = 0.25f/6.0f;
        y[i] = fmaf(c, k1[i] + 2.f*k2[i] + 2.f*k3[i] + k4[i], y[i]);
    }
}

// ---------------- LayerNorm over last dim (128) ----------------
__global__ void __launch_bounds__(128) k_ln(const float* __restrict__ s, float* __restrict__ d){
    int row = blockIdx.x;
    int t = threadIdx.x;
    __shared__ float sh[4];
    float v = s[(size_t)row*HID + t];

    float a = v;
    #pragma unroll
    for (int o = 16; o > 0; o >>= 1) a += __shfl_xor_sync(0xffffffffu, a, o);
    if ((t & 31) == 0) sh[t >> 5] = a;
    __syncthreads();
    float mean = (sh[0]+sh[1]+sh[2]+sh[3]) * (1.f/HID);

    float dv = v - mean;
    float q = dv*dv;
    __syncthreads();
    #pragma unroll
    for (int o = 16; o > 0; o >>= 1) q += __shfl_xor_sync(0xffffffffu, q, o);
    if ((t & 31) == 0) sh[t >> 5] = q;
    __syncthreads();
    float var = (sh[0]+sh[1]+sh[2]+sh[3]) * (1.f/HID);

    d[(size_t)row*HID + t] = dv / sqrtf(var + 1e-5f);
}

// ---------------- launch ----------------
extern "C" void kernel_launch(void* const* d_in, const int* in_sizes, int n_in,
                              void* d_out, int out_size)
{
    const float* inputs = (const float*)d_in[0];
    const int*   src    = (const int*)  d_in[1];
    const int*   dst    = (const int*)  d_in[2];
    const float* w_in   = (const float*)d_in[3];
    const float* b_in   = (const float*)d_in[4];
    const float* w_gat  = (const float*)d_in[5];
    const float* a_l    = (const float*)d_in[6];
    const float* a_r    = (const float*)d_in[7];
    const float* w_W    = (const float*)d_in[8];
    const float* b_W    = (const float*)d_in[9];
    const float* w_U    = (const float*)d_in[10];
    const float* b_U    = (const float*)d_in[11];
    const float* w_o1   = (const float*)d_in[12];
    const float* b_o1   = (const float*)d_in[13];
    const float* w_o2   = (const float*)d_in[14];
    const float* b_o2   = (const float*)d_in[15];
    float* out = (float*)d_out;

    float *hin, *y, *hp, *k1, *k2, *k3, *k4, *tmp;
    int *cnt, *cur, *off, *eidx;
    cudaGetSymbolAddress((void**)&hin, g_hin);
    cudaGetSymbolAddress((void**)&y,   g_y);
    cudaGetSymbolAddress((void**)&hp,  g_hp);
    cudaGetSymbolAddress((void**)&k1,  g_k1);
    cudaGetSymbolAddress((void**)&k2,  g_k2);
    cudaGetSymbolAddress((void**)&k3,  g_k3);
    cudaGetSymbolAddress((void**)&k4,  g_k4);
    cudaGetSymbolAddress((void**)&tmp, g_tmp);
    cudaGetSymbolAddress((void**)&cnt, g_cnt);
    cudaGetSymbolAddress((void**)&cur, g_cur);
    cudaGetSymbolAddress((void**)&off, g_off);
    cudaGetSymbolAddress((void**)&eidx,g_eidx);

    // CSR by destination (deterministic: per-node lists sorted by edge id)
    k_csr_zero <<<(NN+255)/256, 256>>>(cnt, cur);
    k_csr_count<<<(E+255)/256, 256>>>(dst, cnt);
    k_csr_scan <<<1, 1024>>>(cnt, off);
    k_csr_fill <<<(E+255)/256, 256>>>(dst, off, cur, eidx);
    k_csr_sort <<<NN, 32>>>(off, eidx);

    // h = inputs @ w_in + b_in   (layout [SEQ][B][N][HID])
    k_inproj<<<B*SEQ*NN, HID>>>(inputs, w_in, b_in, hin);
    // y = h[:, 0]
    k_copy<<<(M_ROWS*HID+255)/256, 256>>>(hin, y, M_ROWS*HID);

    dim3 gg(125, 2);
    const float dt = 0.25f;
    const int nel = M_ROWS*HID;

    for (int idx = 0; idx < SEQ; idx++){
        for (int s = 0; s < 4; s++){
            // stage 1: k1 = f(y)
            k_gemm<<<gg,128>>>(y, (const float*)0, 0.f, w_gat, (const float*)0,(const float*)0,(const float*)0,(const float*)0, hp, 0);
            k_gat <<<M_ROWS,128>>>(hp, a_l, a_r, off, eidx, src, k1);
            // stage 2: k2 = f(y + 0.5dt k1)
            k_gemm<<<gg,128>>>(y, k1, 0.5f*dt, w_gat, (const float*)0,(const float*)0,(const float*)0,(const float*)0, hp, 0);
            k_gat <<<M_ROWS,128>>>(hp, a_l, a_r, off, eidx, src, k2);
            // stage 3: k3 = f(y + 0.5dt k2)
            k_gemm<<<gg,128>>>(y, k2, 0.5f*dt, w_gat, (const float*)0,(const float*)0,(const float*)0,(const float*)0, hp, 0);
            k_gat <<<M_ROWS,128>>>(hp, a_l, a_r, off, eidx, src, k3);
            // stage 4: k4 = f(y + dt k3)
            k_gemm<<<gg,128>>>(y, k3, dt, w_gat, (const float*)0,(const float*)0,(const float*)0,(const float*)0, hp, 0);
            k_gat <<<M_ROWS,128>>>(hp, a_l, a_r, off, eidx, src, k4);
            // y += dt/6 (k1 + 2k2 + 2k3 + k4)
            k_combine<<<(nel+255)/256, 256>>>(y, k1, k2, k3, k4);
        }
        if (idx > 0){
            // tmp = tanh(y@w_W + h[idx]@w_U + b_W + b_U); y = LN(tmp)
            const float* hidx = hin + (size_t)idx * M_ROWS * HID;
            k_gemm<<<gg,128>>>(y, (const float*)0, 0.f, w_W, hidx, w_U, b_W, b_U, tmp, 1);
            k_ln<<<M_ROWS,128>>>(tmp, y);
        } else {
            k_ln<<<M_ROWS,128>>>(y, y);
        }
    }

    // out = tanh(y@w_o1 + b_o1) @ w_o2 + b_o2
    k_gemm<<<gg,128>>>(y,   (const float*)0, 0.f, w_o1, (const float*)0,(const float*)0, b_o1,(const float*)0, tmp, 1);
    k_gemm<<<gg,128>>>(tmp, (const float*)0, 0.f, w_o2, (const float*)0,(const float*)0, b_o2,(const float*)0, out, 0);
}

// round 3
// speedup vs baseline: 2.5825x; 2.5825x over previous
#include <cuda_runtime.h>
#include <math.h>
#include <float.h>

#define B 8
#define SEQ 12
#define NN 1000
#define E 16000
#define HID 128
#define HEADS 8
#define DH 16
#define M_ROWS (B*NN)          /* 8000 */
#define CAP 64

// ---------------- static device scratch ----------------
__device__ float g_hin[(size_t)SEQ*B*NN*HID];   // [SEQ][B][N][HID]
__device__ float g_y  [(size_t)M_ROWS*HID];
__device__ float g_hp [(size_t)M_ROWS*HID];
__device__ float g_k1 [(size_t)M_ROWS*HID];
__device__ float g_k2 [(size_t)M_ROWS*HID];
__device__ float g_k3 [(size_t)M_ROWS*HID];
__device__ float g_tmp[(size_t)M_ROWS*HID];
__device__ float g_el [(size_t)M_ROWS*HEADS];
__device__ float g_er [(size_t)M_ROWS*HEADS];
__device__ int   g_cnt[NN];
__device__ int   g_cur[NN];
__device__ int   g_off[NN+1];
__device__ int   g_eidx[E];

// ---------------- fused init: inproj + y=h[:,0] + CSR zero ----------------
__global__ void k_init(const float* __restrict__ inp, const float* __restrict__ w_in,
                       const float* __restrict__ b_in, float* __restrict__ hin,
                       float* __restrict__ y, int* cnt, int* cur){
    int row = blockIdx.x;                 // over B*SEQ*NN (input order [B][SEQ][N])
    int t = threadIdx.x;
    if (blockIdx.x < 8){
        int q = blockIdx.x*128 + t;
        if (q < NN){ cnt[q] = 0; cur[q] = 0; }
    }
    int b = row / (SEQ*NN);
    int s = (row / NN) % SEQ;
    int n = row % NN;
    float x0 = inp[(size_t)row*2 + 0];
    float x1 = inp[(size_t)row*2 + 1];
    float v = fmaf(x0, w_in[t], fmaf(x1, w_in[HID+t], b_in[t]));
    hin[(((size_t)s*B + b)*NN + n)*HID + t] = v;
    if (s == 0) y[((size_t)b*NN + n)*HID + t] = v;
}

// ---------------- CSR construction (deterministic: per-node sorted edge ids) ----
__global__ void k_csr_count(const int* __restrict__ dst, int* cnt){
    int e = blockIdx.x*blockDim.x + threadIdx.x;
    if (e < E) atomicAdd(&cnt[dst[e]], 1);
}
__global__ void k_csr_scan(const int* __restrict__ cnt, int* off){
    __shared__ int s[1024];
    int t = threadIdx.x;
    s[t] = (t < NN) ? cnt[t] : 0;
    __syncthreads();
    #pragma unroll
    for (int o = 1; o < 1024; o <<= 1){
        int v = (t >= o) ? s[t-o] : 0;
        __syncthreads();
        s[t] += v;
        __syncthreads();
    }
    if (t == 0) off[0] = 0;
    if (t < NN) off[t+1] = s[t];
}
__global__ void k_csr_fill(const int* __restrict__ dst, const int* __restrict__ off,
                           int* cur, int* eidx){
    int e = blockIdx.x*blockDim.x + threadIdx.x;
    if (e < E){
        int d = dst[e];
        int p = atomicAdd(&cur[d], 1);
        eidx[off[d] + p] = e;
    }
}
__global__ void k_csr_sort(const int* __restrict__ off, int* eidx){
    if (threadIdx.x != 0) return;
    int n = blockIdx.x;
    int a = off[n], b = off[n+1];
    for (int i = a+1; i < b; i++){
        int v = eidx[i]; int j = i-1;
        while (j >= a && eidx[j] > v){ eidx[j+1] = eidx[j]; j--; }
        eidx[j+1] = v;
    }
}

// ---------------- GEMM: C = act( (A0 + c1*A1)@W0 [+ A2@W1] + b0 + b1 ) --------
// Optional epilogue: el/er per-(row,head) attention logit partials (GAT path).
// M=8000, K=N=128. grid (125,2), 256 threads, 4x4 micro-tile per thread.
__global__ void __launch_bounds__(256) k_gemm(
    const float* __restrict__ A0, const float* __restrict__ A1, float c1,
    const float* __restrict__ W0,
    const float* __restrict__ A2, const float* __restrict__ W1,
    const float* __restrict__ b0, const float* __restrict__ b1,
    float* __restrict__ C, int act,
    float* __restrict__ el, float* __restrict__ er,
    const float* __restrict__ a_l, const float* __restrict__ a_r)
{
    __shared__ float sA[64][132];          // padded: bank-clean float4 reads
    int row0    = blockIdx.x * 64;
    int colBase = blockIdx.y * 64;
    int tid = threadIdx.x;
    int tx = tid & 15, ty = tid >> 4;      // tx: col groups, ty: row groups
    int col0 = colBase + tx*4;

    float acc[4][4];
    #pragma unroll
    for (int i=0;i<4;i++)
        #pragma unroll
        for (int j=0;j<4;j++) acc[i][j] = 0.f;

    // ---- load A tile (with fused axpy) ----
    {
        const float4* A04 = (const float4*)A0;
        const float4* A14 = (const float4*)A1;
        for (int i = tid; i < 64*32; i += 256){
            int r = i >> 5, c4 = i & 31;
            float4 v = A04[(size_t)(row0+r)*32 + c4];
            if (A1){
                float4 u = A14[(size_t)(row0+r)*32 + c4];
                v.x = fmaf(c1,u.x,v.x); v.y = fmaf(c1,u.y,v.y);
                v.z = fmaf(c1,u.z,v.z); v.w = fmaf(c1,u.w,v.w);
            }
            *reinterpret_cast<float4*>(&sA[r][c4*4]) = v;
        }
    }
    __syncthreads();
    // ---- product 0 ----
    {
        const float* Wp = W0 + col0;
        #pragma unroll 2
        for (int k = 0; k < HID; k += 4){
            float a[4][4];
            #pragma unroll
            for (int i=0;i<4;i++)
                *reinterpret_cast<float4*>(&a[i][0]) =
                    *reinterpret_cast<const float4*>(&sA[ty*4+i][k]);
            #pragma unroll
            for (int kk=0; kk<4; kk++){
                float4 w = *reinterpret_cast<const float4*>(Wp + (size_t)(k+kk)*HID);
                #pragma unroll
                for (int i=0;i<4;i++){
                    acc[i][0] = fmaf(a[i][kk], w.x, acc[i][0]);
                    acc[i][1] = fmaf(a[i][kk], w.y, acc[i][1]);
                    acc[i][2] = fmaf(a[i][kk], w.z, acc[i][2]);
                    acc[i][3] = fmaf(a[i][kk], w.w, acc[i][3]);
                }
            }
        }
    }
    // ---- optional product 1 ----
    if (A2){
        __syncthreads();
        const float4* A24 = (const float4*)A2;
        for (int i = tid; i < 64*32; i += 256){
            int r = i >> 5, c4 = i & 31;
            *reinterpret_cast<float4*>(&sA[r][c4*4]) = A24[(size_t)(row0+r)*32 + c4];
        }
        __syncthreads();
        const float* Wp = W1 + col0;
        #pragma unroll 2
        for (int k = 0; k < HID; k += 4){
            float a[4][4];
            #pragma unroll
            for (int i=0;i<4;i++)
                *reinterpret_cast<float4*>(&a[i][0]) =
                    *reinterpret_cast<const float4*>(&sA[ty*4+i][k]);
            #pragma unroll
            for (int kk=0; kk<4; kk++){
                float4 w = *reinterpret_cast<const float4*>(Wp + (size_t)(k+kk)*HID);
                #pragma unroll
                for (int i=0;i<4;i++){
                    acc[i][0] = fmaf(a[i][kk], w.x, acc[i][0]);
                    acc[i][1] = fmaf(a[i][kk], w.y, acc[i][1]);
                    acc[i][2] = fmaf(a[i][kk], w.z, acc[i][2]);
                    acc[i][3] = fmaf(a[i][kk], w.w, acc[i][3]);
                }
            }
        }
    }
    // ---- bias + activation + store ----
    float bias[4] = {0.f,0.f,0.f,0.f};
    if (b0){
        #pragma unroll
        for (int j=0;j<4;j++) bias[j] += b0[col0+j];
    }
    if (b1){
        #pragma unroll
        for (int j=0;j<4;j++) bias[j] += b1[col0+j];
    }
    #pragma unroll
    for (int i=0;i<4;i++){
        #pragma unroll
        for (int j=0;j<4;j++) acc[i][j] += bias[j];
    }
    #pragma unroll
    for (int i=0;i<4;i++){
        int r = row0 + ty*4 + i;
        float4 o;
        o.x = acc[i][0]; o.y = acc[i][1]; o.z = acc[i][2]; o.w = acc[i][3];
        if (act){ o.x=tanhf(o.x); o.y=tanhf(o.y); o.z=tanhf(o.z); o.w=tanhf(o.w); }
        *reinterpret_cast<float4*>(C + (size_t)r*HID + col0) = o;
    }
    // ---- GAT logit epilogue: el/er[row][head] (each 64-col block owns 4 heads) ----
    if (el){
        int head = (colBase >> 4) + (tx >> 2);
        int dbase = (tx & 3) * 4;                    // offset within head's 16 dims
        #pragma unroll
        for (int i=0;i<4;i++){
            float pl = 0.f, pr = 0.f;
            #pragma unroll
            for (int j=0;j<4;j++){
                pl = fmaf(acc[i][j], a_l[head*DH + dbase + j], pl);
                pr = fmaf(acc[i][j], a_r[head*DH + dbase + j], pr);
            }
            pl += __shfl_xor_sync(0xffffffffu, pl, 1);
            pl += __shfl_xor_sync(0xffffffffu, pl, 2);
            pr += __shfl_xor_sync(0xffffffffu, pr, 1);
            pr += __shfl_xor_sync(0xffffffffu, pr, 2);
            if ((tx & 3) == 0){
                int r = row0 + ty*4 + i;
                el[(size_t)r*HEADS + head] = pl;
                er[(size_t)r*HEADS + head] = pr;
            }
        }
    }
}

// ---------------- GAT: edge softmax + aggregation (scalar logits, no shfl chains)
// block = (b,n) destination node; 128 threads; head = tid>>4.
// If yin != 0: fused RK4 combine  kout = yin + dtc*(k1 + 2k2 + 2k3 + k4_local)
__global__ void __launch_bounds__(128) k_gat(
    const float* __restrict__ hp, const float* __restrict__ el,
    const float* __restrict__ er,
    const int* __restrict__ off, const int* __restrict__ eidx,
    const int* __restrict__ src, float* __restrict__ kout,
    const float* __restrict__ yin, const float* __restrict__ k1,
    const float* __restrict__ k2, const float* __restrict__ k3, float dtc)
{
    int bn = blockIdx.x;
    int b = bn / NN, n = bn - b*NN;
    int tid = threadIdx.x, head = tid >> 4;

    __shared__ int   s_src[CAP];
    __shared__ float s_w[CAP*HEADS];
    __shared__ float s_pm[16][HEADS];
    __shared__ float s_scale[HEADS], s_runmax[HEADS], s_runsum[HEADS], s_er[HEADS];

    if (tid < HEADS){
        s_er[tid]     = er[(size_t)bn*HEADS + tid];
        s_runmax[tid] = -FLT_MAX;
        s_runsum[tid] = 0.f;
    }
    int e0 = off[n], deg = off[n+1] - e0;
    const float* hb  = hp + (size_t)b*NN*HID;
    const float* elb = el + (size_t)b*NN*HEADS;
    float acc = 0.f;
    __syncthreads();

    for (int base = 0; base < deg; base += CAP){
        int cnt = min(CAP, deg - base);
        if (tid < cnt) s_src[tid] = src[eidx[e0 + base + tid]];
        __syncthreads();
        // logits (leaky relu)
        for (int idx = tid; idx < cnt*HEADS; idx += 128){
            int j = idx >> 3, h = idx & 7;
            float e = elb[(size_t)s_src[j]*HEADS + h] + s_er[h];
            s_w[idx] = (e >= 0.f) ? e : 0.2f*e;
        }
        __syncthreads();
        // per-head max
        { int h = tid & 7, j0 = tid >> 3; float m = -FLT_MAX;
          for (int j = j0; j < cnt; j += 16) m = fmaxf(m, s_w[j*HEADS + h]);
          s_pm[j0][h] = m; }
        __syncthreads();
        if (tid < HEADS){
            float m = -FLT_MAX;
            #pragma unroll
            for (int i=0;i<16;i++) m = fmaxf(m, s_pm[i][tid]);
            float old = s_runmax[tid];
            float nm  = fmaxf(old, m);
            s_scale[tid]  = (old == -FLT_MAX) ? 0.f : __expf(old - nm);
            s_runmax[tid] = nm;
        }
        __syncthreads();
        // exp in-place
        for (int idx = tid; idx < cnt*HEADS; idx += 128){
            int h = idx & 7;
            s_w[idx] = __expf(s_w[idx] - s_runmax[h]);
        }
        acc *= s_scale[head];
        __syncthreads();
        // per-head weight sums
        { int h = tid & 7, j0 = tid >> 3; float ps = 0.f;
          for (int j = j0; j < cnt; j += 16) ps += s_w[j*HEADS + h];
          s_pm[j0][h] = ps; }
        __syncthreads();
        if (tid < HEADS){
            float ps = 0.f;
            #pragma unroll
            for (int i=0;i<16;i++) ps += s_pm[i][tid];
            s_runsum[tid] = s_runsum[tid]*s_scale[tid] + ps;
        }
        // aggregation: acc += w_j * h_src_j[tid]   (unrolled for MLP)
        int j = 0;
        for (; j + 4 <= cnt; j += 4){
            float w0 = s_w[(j+0)*HEADS + head];
            float w1 = s_w[(j+1)*HEADS + head];
            float w2 = s_w[(j+2)*HEADS + head];
            float w3 = s_w[(j+3)*HEADS + head];
            float h0 = hb[(size_t)s_src[j+0]*HID + tid];
            float h1 = hb[(size_t)s_src[j+1]*HID + tid];
            float h2 = hb[(size_t)s_src[j+2]*HID + tid];
            float h3 = hb[(size_t)s_src[j+3]*HID + tid];
            acc = fmaf(w0, h0, acc);
            acc = fmaf(w1, h1, acc);
            acc = fmaf(w2, h2, acc);
            acc = fmaf(w3, h3, acc);
        }
        for (; j < cnt; j++)
            acc = fmaf(s_w[j*HEADS + head], hb[(size_t)s_src[j]*HID + tid], acc);
        __syncthreads();
    }
    float kv = acc / (s_runsum[head] + 1e-16f);
    size_t o = (size_t)bn*HID + tid;
    if (yin){
        kout[o] = yin[o] + dtc*(k1[o] + 2.f*k2[o] + 2.f*k3[o] + kv);
    } else {
        kout[o] = kv;
    }
}

// ---------------- LayerNorm over last dim (128) ----------------
__global__ void __launch_bounds__(128) k_ln(const float* __restrict__ s, float* __restrict__ d){
    int row = blockIdx.x;
    int t = threadIdx.x;
    __shared__ float sh[4];
    float v = s[(size_t)row*HID + t];

    float a = v;
    #pragma unroll
    for (int o = 16; o > 0; o >>= 1) a += __shfl_xor_sync(0xffffffffu, a, o);
    if ((t & 31) == 0) sh[t >> 5] = a;
    __syncthreads();
    float mean = (sh[0]+sh[1]+sh[2]+sh[3]) * (1.f/HID);

    float dv = v - mean;
    float q = dv*dv;
    __syncthreads();
    #pragma unroll
    for (int o = 16; o > 0; o >>= 1) q += __shfl_xor_sync(0xffffffffu, q, o);
    if ((t & 31) == 0) sh[t >> 5] = q;
    __syncthreads();
    float var = (sh[0]+sh[1]+sh[2]+sh[3]) * (1.f/HID);

    d[(size_t)row*HID + t] = dv / sqrtf(var + 1e-5f);
}

// ---------------- launch ----------------
extern "C" void kernel_launch(void* const* d_in, const int* in_sizes, int n_in,
                              void* d_out, int out_size)
{
    const float* inputs = (const float*)d_in[0];
    const int*   src    = (const int*)  d_in[1];
    const int*   dst    = (const int*)  d_in[2];
    const float* w_in   = (const float*)d_in[3];
    const float* b_in   = (const float*)d_in[4];
    const float* w_gat  = (const float*)d_in[5];
    const float* a_l    = (const float*)d_in[6];
    const float* a_r    = (const float*)d_in[7];
    const float* w_W    = (const float*)d_in[8];
    const float* b_W    = (const float*)d_in[9];
    const float* w_U    = (const float*)d_in[10];
    const float* b_U    = (const float*)d_in[11];
    const float* w_o1   = (const float*)d_in[12];
    const float* b_o1   = (const float*)d_in[13];
    const float* w_o2   = (const float*)d_in[14];
    const float* b_o2   = (const float*)d_in[15];
    float* out = (float*)d_out;

    float *hin, *y, *hp, *k1, *k2, *k3, *tmp, *el, *er;
    int *cnt, *cur, *off, *eidx;
    cudaGetSymbolAddress((void**)&hin, g_hin);
    cudaGetSymbolAddress((void**)&y,   g_y);
    cudaGetSymbolAddress((void**)&hp,  g_hp);
    cudaGetSymbolAddress((void**)&k1,  g_k1);
    cudaGetSymbolAddress((void**)&k2,  g_k2);
    cudaGetSymbolAddress((void**)&k3,  g_k3);
    cudaGetSymbolAddress((void**)&tmp, g_tmp);
    cudaGetSymbolAddress((void**)&el,  g_el);
    cudaGetSymbolAddress((void**)&er,  g_er);
    cudaGetSymbolAddress((void**)&cnt, g_cnt);
    cudaGetSymbolAddress((void**)&cur, g_cur);
    cudaGetSymbolAddress((void**)&off, g_off);
    cudaGetSymbolAddress((void**)&eidx,g_eidx);

    const float* F0 = (const float*)0;   // null const input
    float*       FW = (float*)0;         // null mutable output (el/er off)

    // 5 prelude launches (so ncu -s 5 -c 1 captures the first k_gemm)
    k_init     <<<B*SEQ*NN, HID>>>(inputs, w_in, b_in, hin, y, cnt, cur);
    k_csr_count<<<(E+255)/256, 256>>>(dst, cnt);
    k_csr_scan <<<1, 1024>>>(cnt, off);
    k_csr_fill <<<(E+255)/256, 256>>>(dst, off, cur, eidx);
    k_csr_sort <<<NN, 32>>>(off, eidx);

    dim3 gg(125, 2);
    const float dt  = 0.25f;
    const float dtc = dt / 6.0f;

    for (int idx = 0; idx < SEQ; idx++){
        for (int s = 0; s < 4; s++){
            // stage 1: k1 = f(y)
            k_gemm<<<gg,256>>>(y, F0, 0.f, w_gat, F0,F0,F0,F0, hp, 0, el, er, a_l, a_r);
            k_gat <<<M_ROWS,128>>>(hp, el, er, off, eidx, src, k1, F0,F0,F0,F0, 0.f);
            // stage 2: k2 = f(y + 0.5dt k1)
            k_gemm<<<gg,256>>>(y, k1, 0.5f*dt, w_gat, F0,F0,F0,F0, hp, 0, el, er, a_l, a_r);
            k_gat <<<M_ROWS,128>>>(hp, el, er, off, eidx, src, k2, F0,F0,F0,F0, 0.f);
            // stage 3: k3 = f(y + 0.5dt k2)
            k_gemm<<<gg,256>>>(y, k2, 0.5f*dt, w_gat, F0,F0,F0,F0, hp, 0, el, er, a_l, a_r);
            k_gat <<<M_ROWS,128>>>(hp, el, er, off, eidx, src, k3, F0,F0,F0,F0, 0.f);
            // stage 4: k4 = f(y + dt k3), fused with y += dt/6 (k1+2k2+2k3+k4)
            k_gemm<<<gg,256>>>(y, k3, dt, w_gat, F0,F0,F0,F0, hp, 0, el, er, a_l, a_r);
            k_gat <<<M_ROWS,128>>>(hp, el, er, off, eidx, src, y, y, k1, k2, k3, dtc);
        }
        if (idx > 0){
            const float* hidx = hin + (size_t)idx * M_ROWS * HID;
            k_gemm<<<gg,256>>>(y, F0, 0.f, w_W, hidx, w_U, b_W, b_U, tmp, 1, FW,FW,F0,F0);
            k_ln  <<<M_ROWS,128>>>(tmp, y);
        } else {
            k_ln  <<<M_ROWS,128>>>(y, y);
        }
    }

    // out = tanh(y@w_o1 + b_o1) @ w_o2 + b_o2
    k_gemm<<<gg,256>>>(y,   F0, 0.f, w_o1, F0,F0, b_o1,F0, tmp, 1, FW,FW,F0,F0);
    k_gemm<<<gg,256>>>(tmp, F0, 0.f, w_o2, F0,F0, b_o2,F0, out, 0, FW,FW,F0,F0);
}